// round 14
// baseline (speedup 1.0000x reference)
#include <cuda_runtime.h>

// Fused pre-norm attention-downsampling:
//   out[b,s,:] = q[b,s,:] + sum_f (LN(q[b,s]) . LN(k[b,4s+f])) * LN(v[b,4s+f])
// B=4, Sq=2048, Skv=8192, D=1024, factor=4.
// R13: R12 math + software pipelining across 4 rows per CTA.
//  - After the dot loop kills kr (and v loads are in flight), the NEXT row's
//    q+k LDGs are issued into the freed registers -> loads outstanding through
//    reduce2/epilogue, raising DRAM duty cycle.
//  - w/b live in per-thread smem slots (self-written, no barrier) and are
//    re-read at use sites to keep peak registers <= 64 (4 CTAs/SM).

#define DD 1024
#define NT 256
#define NW 8
#define FACTOR 4
#define RPB 4
#define LN_EPS 1e-5f
#define WSTRIDE 96            // 12 values * 8 partials per warp (floats)
#define SMB (NW * WSTRIDE)    // 768 floats of partials; bcast region after

// Batched block reduction of N values (N <= 12), 2 barriers, no SEL chains.
template <int N>
__device__ __forceinline__ void block_reduce(float (&val)[N], float* sm) {
#pragma unroll
    for (int i = 0; i < N; i++) {
        val[i] += __shfl_xor_sync(0xffffffffu, val[i], 16);
        val[i] += __shfl_xor_sync(0xffffffffu, val[i], 8);
    }
    const int w = threadIdx.x >> 5;
    const int l = threadIdx.x & 31;
    if (l < 8) {
#pragma unroll
        for (int i = 0; i < N; i++) sm[w * WSTRIDE + i * 8 + l] = val[i];
    }
    __syncthreads();
    if (threadIdx.x < N) {
        float tot = 0.f;
#pragma unroll
        for (int j = 0; j < NW; j++) {
            const float4 p0 =
                *(const float4*)&sm[j * WSTRIDE + threadIdx.x * 8];
            const float4 p1 =
                *(const float4*)&sm[j * WSTRIDE + threadIdx.x * 8 + 4];
            tot += ((p0.x + p0.y) + (p0.z + p0.w)) +
                   ((p1.x + p1.y) + (p1.z + p1.w));
        }
        sm[SMB + threadIdx.x] = tot;
    }
    __syncthreads();
#pragma unroll
    for (int i = 0; i < N; i += 4) {
        const float4 bb = *(const float4*)&sm[SMB + i];
        val[i] = bb.x;
        if (i + 1 < N) val[i + 1] = bb.y;
        if (i + 2 < N) val[i + 2] = bb.z;
        if (i + 3 < N) val[i + 3] = bb.w;
    }
}

__device__ __forceinline__ float hsum(const float4 a) {
    return (a.x + a.y) + (a.z + a.w);
}
__device__ __forceinline__ float hsq(const float4 a) {
    return (a.x * a.x + a.y * a.y) + (a.z * a.z + a.w * a.w);
}

__global__ __launch_bounds__(NT, 4) void attn_ds_kernel(
    const float* __restrict__ q, const float* __restrict__ k,
    const float* __restrict__ v, const float* __restrict__ lnw,
    const float* __restrict__ lnb, float* __restrict__ out) {
    __shared__ __align__(16) float sm[SMB + 12];
    __shared__ float4 swb[2][NT];   // [0]=weight, [1]=bias, slot per thread

    const int t = threadIdx.x;
    const float invD = 1.0f / (float)DD;

    // Each thread fills and reads ONLY its own slots: no barrier needed.
    swb[0][t] = ((const float4*)lnw)[t];
    swb[1][t] = ((const float4*)lnb)[t];

    const int base = blockIdx.x * RPB;     // rows base..base+3, same batch
    const float4* qg = (const float4*)q;
    const float4* kg = (const float4*)k;
    const float4* vg = (const float4*)v;

    // Prologue: row 0 q + k.
    float4 qv = qg[(size_t)base * (DD / 4) + t];
    float4 kr[FACTOR];
    {
        const size_t kvo =
            ((size_t)(base >> 11) * 8192 + (size_t)(base & 2047) * FACTOR) *
            (DD / 4);
#pragma unroll
        for (int f = 0; f < FACTOR; f++) kr[f] = kg[kvo + f * (DD / 4) + t];
    }

#pragma unroll
    for (int i = 0; i < RPB; i++) {
        const int row = base + i;
        const size_t kvo =
            ((size_t)(row >> 11) * 8192 + (size_t)(row & 2047) * FACTOR) *
            (DD / 4);

        // ---- Phase 1: q + k stats ----
        float r1[10];
        r1[0] = hsum(qv);
        r1[1] = hsq(qv);
#pragma unroll
        for (int f = 0; f < FACTOR; f++) {
            r1[2 + 2 * f] = hsum(kr[f]);
            r1[3 + 2 * f] = hsq(kr[f]);
        }
        block_reduce<10>(r1, sm);

        const float mu = r1[0] * invD;
        const float rs = rsqrtf(fmaf(-mu, mu, r1[1] * invD) + LN_EPS);
        float4 qn;
        {
            const float4 wv = swb[0][t];
            const float4 bv = swb[1][t];
            qn.x = fmaf((qv.x - mu) * rs, wv.x, bv.x);
            qn.y = fmaf((qv.y - mu) * rs, wv.y, bv.y);
            qn.z = fmaf((qv.z - mu) * rs, wv.z, bv.z);
            qn.w = fmaf((qv.w - mu) * rs, wv.w, bv.w);
        }

        // ---- Phase 2: dots (kr dies); v loads issued per f ----
        float4 vr[FACTOR];
        float r2[12];
        {
            const float4 wv = swb[0][t];
            const float4 bv = swb[1][t];
#pragma unroll
            for (int f = 0; f < FACTOR; f++) {
                const float muk = r1[2 + 2 * f] * invD;
                const float rsk =
                    rsqrtf(fmaf(-muk, muk, r1[3 + 2 * f] * invD) + LN_EPS);
                const float4 kv = kr[f];
                const float knx = fmaf((kv.x - muk) * rsk, wv.x, bv.x);
                const float kny = fmaf((kv.y - muk) * rsk, wv.y, bv.y);
                const float knz = fmaf((kv.z - muk) * rsk, wv.z, bv.z);
                const float knw = fmaf((kv.w - muk) * rsk, wv.w, bv.w);
                r2[f] = (knx * qn.x + kny * qn.y) + (knz * qn.z + knw * qn.w);
                vr[f] = vg[kvo + f * (DD / 4) + t];
            }
        }

        // ---- Prefetch next row's q + k into the freed kr slots ----
        float4 nq;
        float4 nkr[FACTOR];
        if (i + 1 < RPB) {
            const int nrow = row + 1;
            const size_t nkvo =
                ((size_t)(nrow >> 11) * 8192 +
                 (size_t)(nrow & 2047) * FACTOR) *
                (DD / 4);
            nq = qg[(size_t)nrow * (DD / 4) + t];
#pragma unroll
            for (int f = 0; f < FACTOR; f++)
                nkr[f] = kg[nkvo + f * (DD / 4) + t];
        }

        // ---- v stats + reduce2 (prefetch LDGs in flight underneath) ----
#pragma unroll
        for (int f = 0; f < FACTOR; f++) {
            r2[4 + f] = hsum(vr[f]);
            r2[8 + f] = hsq(vr[f]);
        }
        block_reduce<12>(r2, sm);

        // ---- Epilogue ----
        float4 acc = qv;
        {
            const float4 wv = swb[0][t];
            const float4 bv = swb[1][t];
#pragma unroll
            for (int f = 0; f < FACTOR; f++) {
                const float wt = r2[f];
                const float muv = r2[4 + f] * invD;
                const float rsv =
                    rsqrtf(fmaf(-muv, muv, r2[8 + f] * invD) + LN_EPS);
                const float4 vv = vr[f];
                acc.x = fmaf(wt, fmaf((vv.x - muv) * rsv, wv.x, bv.x), acc.x);
                acc.y = fmaf(wt, fmaf((vv.y - muv) * rsv, wv.y, bv.y), acc.y);
                acc.z = fmaf(wt, fmaf((vv.z - muv) * rsv, wv.z, bv.z), acc.z);
                acc.w = fmaf(wt, fmaf((vv.w - muv) * rsv, wv.w, bv.w), acc.w);
            }
        }
        ((float4*)out + (size_t)row * (DD / 4))[t] = acc;

        // rotate the pipeline
        if (i + 1 < RPB) {
            qv = nq;
#pragma unroll
            for (int f = 0; f < FACTOR; f++) kr[f] = nkr[f];
        }
    }
}

extern "C" void kernel_launch(void* const* d_in, const int* in_sizes, int n_in,
                              void* d_out, int out_size) {
    const float* q   = (const float*)d_in[0];  // query     [4,2048,1024]
    const float* k   = (const float*)d_in[1];  // key       [4,8192,1024]
    const float* v   = (const float*)d_in[2];  // value     [4,8192,1024]
    const float* lnw = (const float*)d_in[3];  // ln_weight [1024]
    const float* lnb = (const float*)d_in[4];  // ln_bias   [1024]
    float* out = (float*)d_out;                // [4,2048,1024]

    attn_ds_kernel<<<8192 / RPB, NT>>>(q, k, v, lnw, lnb, out);
}

// round 15
// speedup vs baseline: 1.2651x; 1.2651x over previous
#include <cuda_runtime.h>

// Fused pre-norm attention-downsampling:
//   out[b,s,:] = q[b,s,:] + sum_f (LN(q[b,s]) . LN(k[b,4s+f])) * LN(v[b,4s+f])
// B=4, Sq=2048, Skv=8192, D=1024, factor=4.
// R14: SINGLE-reduction formulation. The q.k dot is expanded algebraically:
//   dot_f = rsq*rsk*(S1 - muk*S2 - muq*S3 + muq*muk*C1)
//         + rsq*(S4 - muq*C2) + rsk*(S5_f - muk*C2) + C3
// so all 35 needed sums (q/k/v moments, cross terms, w/b constants) are plain
// linear reductions -> ONE block reduction (2 barriers/row instead of 4),
// no reduce->normalize->reduce dependency chain.

#define DD 1024
#define NT 256
#define NW 8
#define FACTOR 4
#define LN_EPS 1e-5f
#define NR 35
#define WSTRIDE (NR * 8)       // 8 partial classes per warp
#define SMB (NW * WSTRIDE)

// Batched block reduction of N values, 2-level butterfly, 2 barriers.
template <int N>
__device__ __forceinline__ void block_reduce(float (&val)[N], float* sm) {
#pragma unroll
    for (int i = 0; i < N; i++) {
        val[i] += __shfl_xor_sync(0xffffffffu, val[i], 16);
        val[i] += __shfl_xor_sync(0xffffffffu, val[i], 8);
    }
    const int w = threadIdx.x >> 5;
    const int l = threadIdx.x & 31;
    if (l < 8) {
#pragma unroll
        for (int i = 0; i < N; i++) sm[w * WSTRIDE + i * 8 + l] = val[i];
    }
    __syncthreads();
    if (threadIdx.x < N) {
        float tot = 0.f;
#pragma unroll
        for (int j = 0; j < NW; j++) {
            const float4 p0 =
                *(const float4*)&sm[j * WSTRIDE + threadIdx.x * 8];
            const float4 p1 =
                *(const float4*)&sm[j * WSTRIDE + threadIdx.x * 8 + 4];
            tot += ((p0.x + p0.y) + (p0.z + p0.w)) +
                   ((p1.x + p1.y) + (p1.z + p1.w));
        }
        sm[SMB + threadIdx.x] = tot;
    }
    __syncthreads();
#pragma unroll
    for (int i = 0; i < N; i += 4) {
        const float4 bb = *(const float4*)&sm[SMB + i];
        val[i] = bb.x;
        if (i + 1 < N) val[i + 1] = bb.y;
        if (i + 2 < N) val[i + 2] = bb.z;
        if (i + 3 < N) val[i + 3] = bb.w;
    }
}

__device__ __forceinline__ float hsum(const float4 a) {
    return (a.x + a.y) + (a.z + a.w);
}
__device__ __forceinline__ float hsq(const float4 a) {
    return (a.x * a.x + a.y * a.y) + (a.z * a.z + a.w * a.w);
}
__device__ __forceinline__ float hdot(const float4 a, const float4 b) {
    return (a.x * b.x + a.y * b.y) + (a.z * b.z + a.w * b.w);
}

__global__ __launch_bounds__(NT, 4) void attn_ds_kernel(
    const float* __restrict__ q, const float* __restrict__ k,
    const float* __restrict__ v, const float* __restrict__ lnw,
    const float* __restrict__ lnb, float* __restrict__ out) {
    __shared__ __align__(16) float sm[SMB + 36];

    const int bid = blockIdx.x;          // b*2048 + s
    const int b = bid >> 11;
    const int s = bid & 2047;
    const int t = threadIdx.x;
    const float invD = 1.0f / (float)DD;

    const float4* q4 = (const float4*)q + (size_t)bid * (DD / 4);
    const size_t kvo = ((size_t)b * 8192 + (size_t)s * FACTOR) * (DD / 4);
    const float4* k4 = (const float4*)k + kvo;
    const float4* v4 = (const float4*)v + kvo;

    // Front-batch q + 4k + w/b (7 LDG.128); v issued during k partials.
    const float4 qv = q4[t];
    const float4 wq = ((const float4*)lnw)[t];
    const float4 bq = ((const float4*)lnb)[t];
    float4 kr[FACTOR];
#pragma unroll
    for (int f = 0; f < FACTOR; f++) kr[f] = k4[f * (DD / 4) + t];

    // ---- all 35 linear partial sums ----
    // [0]=Σq [1]=Σq² [2]=S2=Σqw² [3]=S4=Σqwb
    // [4+f]=Σk [8+f]=Σk² [12+f]=S1=Σqkw² [16+f]=S3=Σkw² [20+f]=S5=Σkwb
    // [24+f]=Σv [28+f]=Σv² [32]=C1=Σw² [33]=C2=Σwb [34]=C3=Σb²
    float r[NR];
    float4 qw;
    qw.x = qv.x * wq.x; qw.y = qv.y * wq.y;
    qw.z = qv.z * wq.z; qw.w = qv.w * wq.w;
    r[0] = hsum(qv);
    r[1] = hsq(qv);
    r[2] = hdot(qw, wq);
    r[3] = hdot(qw, bq);

    float4 vr[FACTOR];
#pragma unroll
    for (int f = 0; f < FACTOR; f++) {
        const float4 kv = kr[f];
        vr[f] = v4[f * (DD / 4) + t];   // overlap v loads with k partials
        float4 kw;
        kw.x = kv.x * wq.x; kw.y = kv.y * wq.y;
        kw.z = kv.z * wq.z; kw.w = kv.w * wq.w;
        r[4 + f]  = hsum(kv);
        r[8 + f]  = hsq(kv);
        r[12 + f] = hdot(qw, kw);
        r[16 + f] = hdot(kw, wq);
        r[20 + f] = hdot(kw, bq);
    }
#pragma unroll
    for (int f = 0; f < FACTOR; f++) {
        r[24 + f] = hsum(vr[f]);
        r[28 + f] = hsq(vr[f]);
    }
    r[32] = hdot(wq, wq);
    r[33] = hdot(wq, bq);
    r[34] = hdot(bq, bq);

    block_reduce<NR>(r, sm);   // the ONLY reduction

    // ---- scalar math (every thread, redundant but cheap) ----
    const float muq = r[0] * invD;
    const float rsq = rsqrtf(fmaf(-muq, muq, r[1] * invD) + LN_EPS);
    const float S2 = r[2], S4 = r[3];
    const float C1 = r[32], C2 = r[33], C3 = r[34];

    float4 acc = qv;
#pragma unroll
    for (int f = 0; f < FACTOR; f++) {
        const float muk = r[4 + f] * invD;
        const float rsk =
            rsqrtf(fmaf(-muk, muk, r[8 + f] * invD) + LN_EPS);
        const float wt =
            rsq * rsk *
                (r[12 + f] - muk * S2 - muq * r[16 + f] + muq * muk * C1) +
            rsq * (S4 - muq * C2) + rsk * (r[20 + f] - muk * C2) + C3;

        const float muv = r[24 + f] * invD;
        const float rsv =
            rsqrtf(fmaf(-muv, muv, r[28 + f] * invD) + LN_EPS);
        const float4 vv = vr[f];
        acc.x = fmaf(wt, fmaf((vv.x - muv) * rsv, wq.x, bq.x), acc.x);
        acc.y = fmaf(wt, fmaf((vv.y - muv) * rsv, wq.y, bq.y), acc.y);
        acc.z = fmaf(wt, fmaf((vv.z - muv) * rsv, wq.z, bq.z), acc.z);
        acc.w = fmaf(wt, fmaf((vv.w - muv) * rsv, wq.w, bq.w), acc.w);
    }

    ((float4*)out + (size_t)bid * (DD / 4))[t] = acc;
}

extern "C" void kernel_launch(void* const* d_in, const int* in_sizes, int n_in,
                              void* d_out, int out_size) {
    const float* q   = (const float*)d_in[0];  // query     [4,2048,1024]
    const float* k   = (const float*)d_in[1];  // key       [4,8192,1024]
    const float* v   = (const float*)d_in[2];  // value     [4,8192,1024]
    const float* lnw = (const float*)d_in[3];  // ln_weight [1024]
    const float* lnb = (const float*)d_in[4];  // ln_bias   [1024]
    float* out = (float*)d_out;                // [4,2048,1024]

    attn_ds_kernel<<<4 * 2048, NT>>>(q, k, v, lnw, lnb, out);
}